// round 8
// baseline (speedup 1.0000x reference)
#include <cuda_runtime.h>
#include <cuda_fp16.h>
#include <cuda_bf16.h>
#include <cstdint>

#define Nn   32
#define CIN  64
#define COUT 128
#define Vv   25
#define Tlen 300
#define Ss   3
#define VT   7500
#define VV   625
#define EPSf 1e-5f

typedef unsigned long long u64;

// ---- device scratch (allocation-free) ----
__device__ __align__(16) __half g_feat[Ss * Nn * COUT * VT]; // [s][n][o][w*300+t] (184.3 MB)
__device__ __align__(16) float  g_A[Ss * Nn * COUT * VV];    // [s][n][o][v*25+w]  (30.7 MB)
__device__ __align__(16) __half g_Whi[512 * 64];
__device__ __align__(16) __half g_Wlo[512 * 64];
__device__ __align__(16) float g_bias[512];

// ---- scalar/FMA2 helpers ----
__device__ __forceinline__ void fma2(u64& d, u64 a, u64 b) {
    asm("fma.rn.f32x2 %0, %1, %2, %0;" : "+l"(d) : "l"(a), "l"(b));
}
__device__ __forceinline__ u64 dup2(float v) {
    u64 r; asm("mov.b64 %0, {%1, %1};" : "=l"(r) : "f"(v)); return r;
}
__device__ __forceinline__ u64 pack2(float lo, float hi) {
    u64 r; asm("mov.b64 %0, {%1, %2};" : "=l"(r) : "f"(lo), "f"(hi)); return r;
}
__device__ __forceinline__ float lo32(u64 v) { return __uint_as_float((unsigned)v); }
__device__ __forceinline__ float hi32(u64 v) { return __uint_as_float((unsigned)(v >> 32)); }

__device__ __forceinline__ uint32_t smem_u32(const void* p) {
    uint32_t a;
    asm("{ .reg .u64 t; cvta.to.shared.u64 t, %1; cvt.u32.u64 %0, t; }" : "=r"(a) : "l"(p));
    return a;
}

// ---- mma.sync / ldmatrix (sm_80+, no arch-'a' gating) ----
#define LDSM_X4(r, addr) \
    asm volatile("ldmatrix.sync.aligned.m8n8.x4.shared.b16 {%0,%1,%2,%3}, [%4];" \
        : "=r"((r)[0]), "=r"((r)[1]), "=r"((r)[2]), "=r"((r)[3]) : "r"(addr))
#define LDSM_X2T(r, addr) \
    asm volatile("ldmatrix.sync.aligned.m8n8.x2.trans.shared.b16 {%0,%1}, [%2];" \
        : "=r"((r)[0]), "=r"((r)[1]) : "r"(addr))
#define MMA_F16(d, a, b) \
    asm volatile("mma.sync.aligned.m16n8k16.row.col.f32.f16.f16.f32 " \
        "{%0,%1,%2,%3}, {%4,%5,%6,%7}, {%8,%9}, {%0,%1,%2,%3};" \
        : "+f"((d)[0]), "+f"((d)[1]), "+f"((d)[2]), "+f"((d)[3]) \
        : "r"((a)[0]), "r"((a)[1]), "r"((a)[2]), "r"((a)[3]), "r"((b)[0]), "r"((b)[1]))

// ---------------------------------------------------------------------------
// kW: split folded W into fp16 hi/lo + bias
// ---------------------------------------------------------------------------
__global__ void kW(const float* __restrict__ conv3_w, const float* __restrict__ conv3_b,
                   const float* __restrict__ down_w,  const float* __restrict__ down_b,
                   const float* __restrict__ dg, const float* __restrict__ dbeta,
                   const float* __restrict__ dm, const float* __restrict__ dvar) {
    int idx = blockIdx.x * blockDim.x + threadIdx.x;
    if (idx >= 512 * 64) return;
    int r = idx >> 6, k = idx & 63;
    float w;
    if (r < Ss * COUT) {
        w = conv3_w[r * CIN + k];
    } else {
        int o = r - Ss * COUT;
        w = dg[o] * rsqrtf(dvar[o] + EPSf) * down_w[o * CIN + k];
    }
    __half hi = __float2half_rn(w);
    g_Whi[idx] = hi;
    g_Wlo[idx] = __float2half_rn(w - __half2float(hi));
    if (k == 0) {
        float b;
        if (r < Ss * COUT) b = conv3_b[r];
        else {
            int o = r - Ss * COUT;
            float sc = dg[o] * rsqrtf(dvar[o] + EPSf);
            b = sc * (down_b[o] - dm[o]) + dbeta[o];
        }
        g_bias[r] = b;
    }
}

// ---------------------------------------------------------------------------
// kA: g_A = (ada_w . ada_A + ada_b) * PA. grid (20, n, s), 128 threads, FMA2.
// ---------------------------------------------------------------------------
#define KA_SMEM (64 * 16 * 8 + 64 * 125 * 4 + 32 * 4)
__global__ void __launch_bounds__(128)
kA(const float* __restrict__ adaA, const float* __restrict__ PA,
   const float* __restrict__ ada_w, const float* __restrict__ ada_b) {
    extern __shared__ char smA[];
    u64*   Wp  = (u64*)smA;
    float* Xa  = (float*)(smA + 64 * 16 * 8);
    float* bsm = (float*)(smA + 64 * 16 * 8 + 64 * 125 * 4);

    int tid = threadIdx.x;
    int s = blockIdx.z, n = blockIdx.y;
    int g = blockIdx.x & 3;
    int vw0 = (blockIdx.x >> 2) * 125;

    const float* wsrc = ada_w + s * COUT * CIN + g * 32 * CIN;
    for (int idx = tid; idx < 64 * 16; idx += 128) {
        int i = idx >> 4, op = idx & 15;
        Wp[i * 16 + op] = pack2(wsrc[(2 * op) * CIN + i], wsrc[(2 * op + 1) * CIN + i]);
    }
    for (int idx = tid; idx < 64 * 125; idx += 128) {
        int i = idx / 125, j = idx % 125;
        Xa[i * 125 + j] = adaA[(size_t)(n * CIN + i) * VV + vw0 + j];
    }
    if (tid < 32) bsm[tid] = ada_b[s * COUT + g * 32 + tid];
    __syncthreads();
    if (tid >= 125) return;

    int vw = vw0 + tid;
    float pa = PA[s * VV + vw];

    u64 acc[16];
#pragma unroll
    for (int p = 0; p < 16; p++) acc[p] = 0ull;

#pragma unroll 8
    for (int i = 0; i < CIN; i++) {
        u64 f2 = dup2(Xa[i * 125 + tid]);
        const ulonglong2* wr = (const ulonglong2*)(Wp + i * 16);
#pragma unroll
        for (int p = 0; p < 8; p++) {
            ulonglong2 wv = wr[p];
            fma2(acc[2 * p],     wv.x, f2);
            fma2(acc[2 * p + 1], wv.y, f2);
        }
    }
    float* outp = g_A + ((size_t)((s * Nn + n) * COUT) + g * 32) * VV + vw;
#pragma unroll
    for (int p = 0; p < 16; p++) {
        outp[(size_t)(2 * p) * VV]     = (lo32(acc[p]) + bsm[2 * p])     * pa;
        outp[(size_t)(2 * p + 1) * VV] = (hi32(acc[p]) + bsm[2 * p + 1]) * pa;
    }
}

// ---------------------------------------------------------------------------
// kB_m: tensor GEMM C[128r x 128c] = W[128x64] @ X[64 x 128c].
// X staged [k][PADC] fp16 (no transpose), B frags via ldmatrix.trans.
// rg<3: 1 MMA term -> g_feat fp16; rg==3: 3 terms (split fp16) -> d_out fp32.
// grid (59, 4, 32), 256 threads.
// ---------------------------------------------------------------------------
#define PADK 72
#define PADC 136
#define WHI_OFF 0
#define WLO_OFF (128 * PADK * 2)                // 18432
#define XHI_OFF (WLO_OFF + 128 * PADK * 2)      // 36864
#define XLO_OFF (XHI_OFF + 64 * PADC * 2)       // 54272
#define BIAS_OFF (XLO_OFF + 64 * PADC * 2)      // 71680
#define KBM_SMEM (BIAS_OFF + 128 * 4)           // 72192
__global__ void __launch_bounds__(256)
kB_m(const float* __restrict__ x, float* __restrict__ out) {
    extern __shared__ char sm[];
    __half* Whi_s = (__half*)(sm + WHI_OFF);
    __half* Wlo_s = (__half*)(sm + WLO_OFF);
    __half* Xhi_s = (__half*)(sm + XHI_OFF);
    __half* Xlo_s = (__half*)(sm + XLO_OFF);
    float* bias_s = (float*)(sm + BIAS_OFF);
    float* Cs = (float*)sm;   // reuse after mainloop: [128][132]

    int tid = threadIdx.x;
    int wid = tid >> 5, lane = tid & 31;
    int n = blockIdx.z, rg = blockIdx.y;
    int c0 = blockIdx.x * 128;
    int r0 = rg * 128;
    int ncols = VT - c0; if (ncols > 128) ncols = 128;   // 128 or 76 (mult of 4)
    bool isRes = (rg == 3);

    // ---- stage W hi (and lo only for residual rg) ----
    for (int idx = tid; idx < 1024; idx += 256) {
        int row = idx >> 3, kc = (idx & 7) * 8;
        uint4 v = *(const uint4*)(g_Whi + (size_t)(r0 + row) * 64 + kc);
        *(uint4*)(Whi_s + row * PADK + kc) = v;
    }
    if (isRes) {
        for (int idx = tid; idx < 1024; idx += 256) {
            int row = idx >> 3, kc = (idx & 7) * 8;
            uint4 v = *(const uint4*)(g_Wlo + (size_t)(r0 + row) * 64 + kc);
            *(uint4*)(Wlo_s + row * PADK + kc) = v;
        }
    }
    if (tid < 128) bias_s[tid] = g_bias[r0 + tid];

    // ---- stage X [k][c] fp16, split from fp32 (lo only for residual) ----
    for (int idx = tid; idx < 64 * 32; idx += 256) {
        int k = idx >> 5, c4 = (idx & 31) << 2;
        float4 xv = make_float4(0.f, 0.f, 0.f, 0.f);
        if (c4 < ncols) xv = *(const float4*)(x + (size_t)(n * CIN + k) * VT + c0 + c4);
        __half h0 = __float2half_rn(xv.x), h1 = __float2half_rn(xv.y);
        __half h2 = __float2half_rn(xv.z), h3 = __float2half_rn(xv.w);
        __half2 p0(h0, h1), p1(h2, h3);
        uint2 pk; pk.x = *(unsigned*)&p0; pk.y = *(unsigned*)&p1;
        *(uint2*)(Xhi_s + k * PADC + c4) = pk;
        if (isRes) {
            __half2 q0(__float2half_rn(xv.x - __half2float(h0)),
                       __float2half_rn(xv.y - __half2float(h1)));
            __half2 q1(__float2half_rn(xv.z - __half2float(h2)),
                       __float2half_rn(xv.w - __half2float(h3)));
            uint2 pl; pl.x = *(unsigned*)&q0; pl.y = *(unsigned*)&q1;
            *(uint2*)(Xlo_s + k * PADC + c4) = pl;
        }
    }
    __syncthreads();

    int wm0 = (wid & 1) * 64;
    int wn0 = (wid >> 1) * 32;
    uint32_t sbase = smem_u32(sm);

    float acc[4][4][4];
#pragma unroll
    for (int mi = 0; mi < 4; mi++)
#pragma unroll
        for (int ni = 0; ni < 4; ni++)
#pragma unroll
            for (int q = 0; q < 4; q++) acc[mi][ni][q] = 0.f;

#pragma unroll
    for (int k0 = 0; k0 < 64; k0 += 16) {
        uint32_t a_hi[4][4], b_hi[4][2];
#pragma unroll
        for (int mi = 0; mi < 4; mi++) {
            int row = wm0 + mi * 16 + (lane & 15);
            int col = k0 + (lane >> 4) * 8;
            LDSM_X4(a_hi[mi], sbase + WHI_OFF + (uint32_t)(row * PADK + col) * 2);
        }
#pragma unroll
        for (int ni = 0; ni < 4; ni++) {
            int krow = k0 + (lane & 15);
            LDSM_X2T(b_hi[ni], sbase + XHI_OFF + (uint32_t)(krow * PADC + wn0 + ni * 8) * 2);
        }
#pragma unroll
        for (int mi = 0; mi < 4; mi++)
#pragma unroll
            for (int ni = 0; ni < 4; ni++)
                MMA_F16(acc[mi][ni], a_hi[mi], b_hi[ni]);

        if (isRes) {
            uint32_t a_lo[4][4], b_lo[4][2];
#pragma unroll
            for (int mi = 0; mi < 4; mi++) {
                int row = wm0 + mi * 16 + (lane & 15);
                int col = k0 + (lane >> 4) * 8;
                LDSM_X4(a_lo[mi], sbase + WLO_OFF + (uint32_t)(row * PADK + col) * 2);
            }
#pragma unroll
            for (int ni = 0; ni < 4; ni++) {
                int krow = k0 + (lane & 15);
                LDSM_X2T(b_lo[ni], sbase + XLO_OFF + (uint32_t)(krow * PADC + wn0 + ni * 8) * 2);
            }
#pragma unroll
            for (int mi = 0; mi < 4; mi++)
#pragma unroll
                for (int ni = 0; ni < 4; ni++) {
                    MMA_F16(acc[mi][ni], a_hi[mi], b_lo[ni]);
                    MMA_F16(acc[mi][ni], a_lo[mi], b_hi[ni]);
                }
        }
    }

    __syncthreads();

#pragma unroll
    for (int mi = 0; mi < 4; mi++)
#pragma unroll
        for (int ni = 0; ni < 4; ni++) {
            int r = wm0 + mi * 16 + (lane >> 2);
            int c = wn0 + ni * 8 + (lane & 3) * 2;
            *(float2*)(Cs + r * 132 + c)       = make_float2(acc[mi][ni][0], acc[mi][ni][1]);
            *(float2*)(Cs + (r + 8) * 132 + c) = make_float2(acc[mi][ni][2], acc[mi][ni][3]);
        }
    __syncthreads();

    for (int idx = tid; idx < 128 * 32; idx += 256) {
        int row = idx >> 5, c = (idx & 31) * 4;
        if (c >= ncols) continue;
        float4 v = *(float4*)(Cs + row * 132 + c);
        float b = bias_s[row];
        v.x += b; v.y += b; v.z += b; v.w += b;
        if (!isRes) {
            __half2 h0 = __floats2half2_rn(v.x, v.y);
            __half2 h1 = __floats2half2_rn(v.z, v.w);
            uint2 pk; pk.x = *(unsigned*)&h0; pk.y = *(unsigned*)&h1;
            *(uint2*)(g_feat + (size_t)((rg * Nn + n) * COUT + row) * VT + c0 + c) = pk;
        } else {
            *(float4*)(out + (size_t)(n * COUT + row) * VT + c0 + c) = v;
        }
    }
}

// ---------------------------------------------------------------------------
// kC_m: per (o, n): Out[25 x 300] = A[25 x 75] @ feat[75 x 300] (fp16 mma),
// then bn + residual(read from out) + relu. 256 threads (8 warps x 40 cols).
// ---------------------------------------------------------------------------
#define FS  312
#define CSd 308
#define KCM_A   (80 * FS * 2)          // 49920
#define KCM_SMEM (KCM_A + 32 * 80 * 2) // 55040
__global__ void __launch_bounds__(256)
kC_m(const float* __restrict__ bn_g, const float* __restrict__ bn_b,
     const float* __restrict__ bn_m, const float* __restrict__ bn_v,
     float* __restrict__ out) {
    extern __shared__ char sm[];
    __half* feat_s = (__half*)sm;           // [k=sw 80][t FS]
    __half* A_s    = (__half*)(sm + KCM_A); // [v 32][k 80]
    float*  Cs     = (float*)sm;            // reuse: [32][CSd]

    int tid = threadIdx.x;
    int wid = tid >> 5, lane = tid & 31;
    int o = blockIdx.x, n = blockIdx.y;

    // stage feat fp16 via uint2 (4 halves) — 8B alignment guaranteed
    for (int idx = tid; idx < 80 * 78; idx += 256) {
        int row = idx / 78, c4 = (idx % 78) * 4;
        uint2 val = make_uint2(0, 0);
        if (row < 75 && c4 < 300) {
            int s = row / 25, w = row % 25;
            val = *(const uint2*)(g_feat + (size_t)((s * Nn + n) * COUT + o) * VT + w * 300 + c4);
        }
        *(uint2*)(feat_s + row * FS + c4) = val;
    }
    // stage A fp16 (zero-padded to 32 x 80)
    for (int idx = tid; idx < 32 * 80; idx += 256) {
        int v = idx / 80, k = idx % 80;
        float av = 0.f;
        if (v < 25 && k < 75) {
            int s = k / 25, w = k % 25;
            av = g_A[(size_t)((s * Nn + n) * COUT + o) * VV + v * 25 + w];
        }
        A_s[v * 80 + k] = __float2half_rn(av);
    }
    __syncthreads();

    uint32_t sb = smem_u32(sm);
    int wn0 = wid * 40;

    float acc[2][5][4];
#pragma unroll
    for (int mi = 0; mi < 2; mi++)
#pragma unroll
        for (int ni = 0; ni < 5; ni++)
#pragma unroll
            for (int q = 0; q < 4; q++) acc[mi][ni][q] = 0.f;

#pragma unroll
    for (int k0 = 0; k0 < 80; k0 += 16) {
        uint32_t a[2][4];
#pragma unroll
        for (int mi = 0; mi < 2; mi++) {
            int row = mi * 16 + (lane & 15);
            int col = k0 + (lane >> 4) * 8;
            LDSM_X4(a[mi], sb + KCM_A + (uint32_t)(row * 80 + col) * 2);
        }
        uint32_t b[5][2];
#pragma unroll
        for (int ni = 0; ni < 5; ni++) {
            int krow = k0 + (lane & 15);
            LDSM_X2T(b[ni], sb + (uint32_t)(krow * FS + wn0 + ni * 8) * 2);
        }
#pragma unroll
        for (int mi = 0; mi < 2; mi++)
#pragma unroll
            for (int ni = 0; ni < 5; ni++)
                MMA_F16(acc[mi][ni], a[mi], b[ni]);
    }

    __syncthreads();

#pragma unroll
    for (int mi = 0; mi < 2; mi++)
#pragma unroll
        for (int ni = 0; ni < 5; ni++) {
            int c = wn0 + ni * 8 + (lane & 3) * 2;
            if (c < 304) {
                int r = mi * 16 + (lane >> 2);
                *(float2*)(Cs + r * CSd + c)       = make_float2(acc[mi][ni][0], acc[mi][ni][1]);
                *(float2*)(Cs + (r + 8) * CSd + c) = make_float2(acc[mi][ni][2], acc[mi][ni][3]);
            }
        }
    __syncthreads();

    float scale = bn_g[o] * rsqrtf(bn_v[o] + EPSf);
    float shift = bn_b[o] - bn_m[o] * scale;
    for (int idx = tid; idx < 25 * 75; idx += 256) {
        int v = idx / 75, t4 = (idx % 75) * 4;
        float4 g = *(float4*)(Cs + v * CSd + t4);
        float* op = out + ((size_t)n * COUT + o) * VT + v * 300 + t4;
        float4 r = *(float4*)op;
        r.x = fmaxf(fmaf(g.x, scale, shift) + r.x, 0.f);
        r.y = fmaxf(fmaf(g.y, scale, shift) + r.y, 0.f);
        r.z = fmaxf(fmaf(g.z, scale, shift) + r.z, 0.f);
        r.w = fmaxf(fmaf(g.w, scale, shift) + r.w, 0.f);
        *(float4*)op = r;
    }
}

// ---------------------------------------------------------------------------
extern "C" void kernel_launch(void* const* d_in, const int* in_sizes, int n_in,
                              void* d_out, int out_size) {
    const float* x       = (const float*)d_in[0];
    const float* ada_A   = (const float*)d_in[1];
    const float* PA      = (const float*)d_in[2];
    const float* conv3_w = (const float*)d_in[3];
    const float* conv3_b = (const float*)d_in[4];
    const float* ada_w   = (const float*)d_in[5];
    const float* ada_b   = (const float*)d_in[6];
    const float* bn_g    = (const float*)d_in[7];
    const float* bn_b    = (const float*)d_in[8];
    const float* bn_m    = (const float*)d_in[9];
    const float* bn_v    = (const float*)d_in[10];
    const float* down_w  = (const float*)d_in[11];
    const float* down_b  = (const float*)d_in[12];
    const float* dbn_g   = (const float*)d_in[13];
    const float* dbn_b   = (const float*)d_in[14];
    const float* dbn_m   = (const float*)d_in[15];
    const float* dbn_v   = (const float*)d_in[16];
    float* out = (float*)d_out;

    cudaFuncSetAttribute(kA,   cudaFuncAttributeMaxDynamicSharedMemorySize, KA_SMEM);
    cudaFuncSetAttribute(kB_m, cudaFuncAttributeMaxDynamicSharedMemorySize, KBM_SMEM);
    cudaFuncSetAttribute(kC_m, cudaFuncAttributeMaxDynamicSharedMemorySize, KCM_SMEM);

    kW<<<64, 512>>>(conv3_w, conv3_b, down_w, down_b, dbn_g, dbn_b, dbn_m, dbn_v);
    kA<<<dim3(20, Nn, Ss), 128, KA_SMEM>>>(ada_A, PA, ada_w, ada_b);
    kB_m<<<dim3(59, 4, Nn), 256, KBM_SMEM>>>(x, out);
    kC_m<<<dim3(COUT, Nn), 256, KCM_SMEM>>>(bn_g, bn_b, bn_m, bn_v, out);
}

// round 9
// speedup vs baseline: 1.0253x; 1.0253x over previous
#include <cuda_runtime.h>
#include <cuda_fp16.h>
#include <cuda_bf16.h>
#include <cstdint>

#define Nn   32
#define CIN  64
#define COUT 128
#define Vv   25
#define Tlen 300
#define Ss   3
#define VT   7500
#define VV   625
#define EPSf 1e-5f

typedef unsigned long long u64;

// ---- device scratch (allocation-free) ----
__device__ __align__(16) __half g_feat[Ss * Nn * COUT * VT]; // [s][n][o][w*300+t] (184.3 MB)
__device__ __align__(16) float  g_A[Ss * Nn * COUT * VV];    // [s][n][o][v*25+w]  (30.7 MB)
__device__ __align__(16) __half g_Xhi[Nn * CIN * VT];        // fp16 hi of x (30.7 MB)
__device__ __align__(16) __half g_Xlo[Nn * CIN * VT];        // fp16 lo of x (30.7 MB)
__device__ __align__(16) __half g_Whi[512 * 64];
__device__ __align__(16) __half g_Wlo[512 * 64];
__device__ __align__(16) float g_bias[512];

// ---- scalar/FMA2 helpers ----
__device__ __forceinline__ void fma2(u64& d, u64 a, u64 b) {
    asm("fma.rn.f32x2 %0, %1, %2, %0;" : "+l"(d) : "l"(a), "l"(b));
}
__device__ __forceinline__ u64 dup2(float v) {
    u64 r; asm("mov.b64 %0, {%1, %1};" : "=l"(r) : "f"(v)); return r;
}
__device__ __forceinline__ u64 pack2(float lo, float hi) {
    u64 r; asm("mov.b64 %0, {%1, %2};" : "=l"(r) : "f"(lo), "f"(hi)); return r;
}
__device__ __forceinline__ float lo32(u64 v) { return __uint_as_float((unsigned)v); }
__device__ __forceinline__ float hi32(u64 v) { return __uint_as_float((unsigned)(v >> 32)); }

__device__ __forceinline__ uint32_t smem_u32(const void* p) {
    uint32_t a;
    asm("{ .reg .u64 t; cvta.to.shared.u64 t, %1; cvt.u32.u64 %0, t; }" : "=r"(a) : "l"(p));
    return a;
}

// ---- mma.sync / ldmatrix (sm_80+, no arch-'a' gating) ----
#define LDSM_X4(r, addr) \
    asm volatile("ldmatrix.sync.aligned.m8n8.x4.shared.b16 {%0,%1,%2,%3}, [%4];" \
        : "=r"((r)[0]), "=r"((r)[1]), "=r"((r)[2]), "=r"((r)[3]) : "r"(addr))
#define LDSM_X2T(r, addr) \
    asm volatile("ldmatrix.sync.aligned.m8n8.x2.trans.shared.b16 {%0,%1}, [%2];" \
        : "=r"((r)[0]), "=r"((r)[1]) : "r"(addr))
#define MMA_F16(d, a, b) \
    asm volatile("mma.sync.aligned.m16n8k16.row.col.f32.f16.f16.f32 " \
        "{%0,%1,%2,%3}, {%4,%5,%6,%7}, {%8,%9}, {%0,%1,%2,%3};" \
        : "+f"((d)[0]), "+f"((d)[1]), "+f"((d)[2]), "+f"((d)[3]) \
        : "r"((a)[0]), "r"((a)[1]), "r"((a)[2]), "r"((a)[3]), "r"((b)[0]), "r"((b)[1]))

// ---------------------------------------------------------------------------
// kX: pre-split x (fp32) into fp16 hi/lo, linear layout identical to x.
// ---------------------------------------------------------------------------
__global__ void kX(const float* __restrict__ x) {
    size_t i4 = ((size_t)blockIdx.x * blockDim.x + threadIdx.x) * 4;
    if (i4 >= (size_t)Nn * CIN * VT) return;
    float4 v = *(const float4*)(x + i4);
    __half h0 = __float2half_rn(v.x), h1 = __float2half_rn(v.y);
    __half h2 = __float2half_rn(v.z), h3 = __float2half_rn(v.w);
    __half2 p0(h0, h1), p1(h2, h3);
    uint2 ph; ph.x = *(unsigned*)&p0; ph.y = *(unsigned*)&p1;
    *(uint2*)(g_Xhi + i4) = ph;
    __half2 q0(__float2half_rn(v.x - __half2float(h0)), __float2half_rn(v.y - __half2float(h1)));
    __half2 q1(__float2half_rn(v.z - __half2float(h2)), __float2half_rn(v.w - __half2float(h3)));
    uint2 pl; pl.x = *(unsigned*)&q0; pl.y = *(unsigned*)&q1;
    *(uint2*)(g_Xlo + i4) = pl;
}

// ---------------------------------------------------------------------------
// kW: split folded W into fp16 hi/lo + bias
// ---------------------------------------------------------------------------
__global__ void kW(const float* __restrict__ conv3_w, const float* __restrict__ conv3_b,
                   const float* __restrict__ down_w,  const float* __restrict__ down_b,
                   const float* __restrict__ dg, const float* __restrict__ dbeta,
                   const float* __restrict__ dm, const float* __restrict__ dvar) {
    int idx = blockIdx.x * blockDim.x + threadIdx.x;
    if (idx >= 512 * 64) return;
    int r = idx >> 6, k = idx & 63;
    float w;
    if (r < Ss * COUT) {
        w = conv3_w[r * CIN + k];
    } else {
        int o = r - Ss * COUT;
        w = dg[o] * rsqrtf(dvar[o] + EPSf) * down_w[o * CIN + k];
    }
    __half hi = __float2half_rn(w);
    g_Whi[idx] = hi;
    g_Wlo[idx] = __float2half_rn(w - __half2float(hi));
    if (k == 0) {
        float b;
        if (r < Ss * COUT) b = conv3_b[r];
        else {
            int o = r - Ss * COUT;
            float sc = dg[o] * rsqrtf(dvar[o] + EPSf);
            b = sc * (down_b[o] - dm[o]) + dbeta[o];
        }
        g_bias[r] = b;
    }
}

// ---------------------------------------------------------------------------
// kA: g_A = (ada_w . ada_A + ada_b) * PA. grid (20, n, s), 128 threads, FMA2.
// ---------------------------------------------------------------------------
#define KA_SMEM (64 * 16 * 8 + 64 * 125 * 4 + 32 * 4)
__global__ void __launch_bounds__(128)
kA(const float* __restrict__ adaA, const float* __restrict__ PA,
   const float* __restrict__ ada_w, const float* __restrict__ ada_b) {
    extern __shared__ char smA[];
    u64*   Wp  = (u64*)smA;
    float* Xa  = (float*)(smA + 64 * 16 * 8);
    float* bsm = (float*)(smA + 64 * 16 * 8 + 64 * 125 * 4);

    int tid = threadIdx.x;
    int s = blockIdx.z, n = blockIdx.y;
    int g = blockIdx.x & 3;
    int vw0 = (blockIdx.x >> 2) * 125;

    const float* wsrc = ada_w + s * COUT * CIN + g * 32 * CIN;
    for (int idx = tid; idx < 64 * 16; idx += 128) {
        int i = idx >> 4, op = idx & 15;
        Wp[i * 16 + op] = pack2(wsrc[(2 * op) * CIN + i], wsrc[(2 * op + 1) * CIN + i]);
    }
    for (int idx = tid; idx < 64 * 125; idx += 128) {
        int i = idx / 125, j = idx % 125;
        Xa[i * 125 + j] = adaA[(size_t)(n * CIN + i) * VV + vw0 + j];
    }
    if (tid < 32) bsm[tid] = ada_b[s * COUT + g * 32 + tid];
    __syncthreads();
    if (tid >= 125) return;

    int vw = vw0 + tid;
    float pa = PA[s * VV + vw];

    u64 acc[16];
#pragma unroll
    for (int p = 0; p < 16; p++) acc[p] = 0ull;

#pragma unroll 8
    for (int i = 0; i < CIN; i++) {
        u64 f2 = dup2(Xa[i * 125 + tid]);
        const ulonglong2* wr = (const ulonglong2*)(Wp + i * 16);
#pragma unroll
        for (int p = 0; p < 8; p++) {
            ulonglong2 wv = wr[p];
            fma2(acc[2 * p],     wv.x, f2);
            fma2(acc[2 * p + 1], wv.y, f2);
        }
    }
    float* outp = g_A + ((size_t)((s * Nn + n) * COUT) + g * 32) * VV + vw;
#pragma unroll
    for (int p = 0; p < 16; p++) {
        outp[(size_t)(2 * p) * VV]     = (lo32(acc[p]) + bsm[2 * p])     * pa;
        outp[(size_t)(2 * p + 1) * VV] = (hi32(acc[p]) + bsm[2 * p + 1]) * pa;
    }
}

// ---------------------------------------------------------------------------
// kB_m: tensor GEMM C[128r x 128c] = W[128x64] @ X[64 x 128c].
// X staged [k][PADC] fp16 via uint2 copies from pre-split g_Xhi/g_Xlo.
// rg<3: 1 MMA term -> g_feat fp16; rg==3: 3 terms (split fp16) -> d_out fp32.
// grid (59, 4, 32), 256 threads.
// ---------------------------------------------------------------------------
#define PADK 72
#define PADC 136
#define WHI_OFF 0
#define WLO_OFF (128 * PADK * 2)                // 18432
#define XHI_OFF (WLO_OFF + 128 * PADK * 2)      // 36864
#define XLO_OFF (XHI_OFF + 64 * PADC * 2)       // 54272
#define BIAS_OFF (XLO_OFF + 64 * PADC * 2)      // 71680
#define KBM_SMEM (BIAS_OFF + 128 * 4)           // 72192
__global__ void __launch_bounds__(256)
kB_m(float* __restrict__ out) {
    extern __shared__ char sm[];
    __half* Whi_s = (__half*)(sm + WHI_OFF);
    __half* Wlo_s = (__half*)(sm + WLO_OFF);
    __half* Xhi_s = (__half*)(sm + XHI_OFF);
    __half* Xlo_s = (__half*)(sm + XLO_OFF);
    float* bias_s = (float*)(sm + BIAS_OFF);
    float* Cs = (float*)sm;   // reuse after mainloop: [128][132]

    int tid = threadIdx.x;
    int wid = tid >> 5, lane = tid & 31;
    int n = blockIdx.z, rg = blockIdx.y;
    int c0 = blockIdx.x * 128;
    int r0 = rg * 128;
    int ncols = VT - c0; if (ncols > 128) ncols = 128;   // 128 or 76 (mult of 4)
    bool isRes = (rg == 3);

    // ---- stage W hi (and lo only for residual rg) ----
    for (int idx = tid; idx < 1024; idx += 256) {
        int row = idx >> 3, kc = (idx & 7) * 8;
        uint4 v = *(const uint4*)(g_Whi + (size_t)(r0 + row) * 64 + kc);
        *(uint4*)(Whi_s + row * PADK + kc) = v;
    }
    if (isRes) {
        for (int idx = tid; idx < 1024; idx += 256) {
            int row = idx >> 3, kc = (idx & 7) * 8;
            uint4 v = *(const uint4*)(g_Wlo + (size_t)(r0 + row) * 64 + kc);
            *(uint4*)(Wlo_s + row * PADK + kc) = v;
        }
    }
    if (tid < 128) bias_s[tid] = g_bias[r0 + tid];

    // ---- stage X [k][c] fp16 straight copy (uint2; row base 8B-aligned) ----
    for (int idx = tid; idx < 64 * 32; idx += 256) {
        int k = idx >> 5, c4 = (idx & 31) << 2;
        uint2 v = make_uint2(0u, 0u);
        if (c4 < ncols) v = *(const uint2*)(g_Xhi + (size_t)(n * CIN + k) * VT + c0 + c4);
        *(uint2*)(Xhi_s + k * PADC + c4) = v;
        if (isRes) {
            uint2 vl = make_uint2(0u, 0u);
            if (c4 < ncols) vl = *(const uint2*)(g_Xlo + (size_t)(n * CIN + k) * VT + c0 + c4);
            *(uint2*)(Xlo_s + k * PADC + c4) = vl;
        }
    }
    __syncthreads();

    int wm0 = (wid & 1) * 64;
    int wn0 = (wid >> 1) * 32;
    uint32_t sbase = smem_u32(sm);

    float acc[4][4][4];
#pragma unroll
    for (int mi = 0; mi < 4; mi++)
#pragma unroll
        for (int ni = 0; ni < 4; ni++)
#pragma unroll
            for (int q = 0; q < 4; q++) acc[mi][ni][q] = 0.f;

#pragma unroll
    for (int k0 = 0; k0 < 64; k0 += 16) {
        uint32_t a_hi[4][4], b_hi[4][2];
#pragma unroll
        for (int mi = 0; mi < 4; mi++) {
            int row = wm0 + mi * 16 + (lane & 15);
            int col = k0 + (lane >> 4) * 8;
            LDSM_X4(a_hi[mi], sbase + WHI_OFF + (uint32_t)(row * PADK + col) * 2);
        }
#pragma unroll
        for (int ni = 0; ni < 4; ni++) {
            int krow = k0 + (lane & 15);
            LDSM_X2T(b_hi[ni], sbase + XHI_OFF + (uint32_t)(krow * PADC + wn0 + ni * 8) * 2);
        }
#pragma unroll
        for (int mi = 0; mi < 4; mi++)
#pragma unroll
            for (int ni = 0; ni < 4; ni++)
                MMA_F16(acc[mi][ni], a_hi[mi], b_hi[ni]);

        if (isRes) {
            uint32_t a_lo[4][4], b_lo[4][2];
#pragma unroll
            for (int mi = 0; mi < 4; mi++) {
                int row = wm0 + mi * 16 + (lane & 15);
                int col = k0 + (lane >> 4) * 8;
                LDSM_X4(a_lo[mi], sbase + WLO_OFF + (uint32_t)(row * PADK + col) * 2);
            }
#pragma unroll
            for (int ni = 0; ni < 4; ni++) {
                int krow = k0 + (lane & 15);
                LDSM_X2T(b_lo[ni], sbase + XLO_OFF + (uint32_t)(krow * PADC + wn0 + ni * 8) * 2);
            }
#pragma unroll
            for (int mi = 0; mi < 4; mi++)
#pragma unroll
                for (int ni = 0; ni < 4; ni++) {
                    MMA_F16(acc[mi][ni], a_hi[mi], b_lo[ni]);
                    MMA_F16(acc[mi][ni], a_lo[mi], b_hi[ni]);
                }
        }
    }

    __syncthreads();

#pragma unroll
    for (int mi = 0; mi < 4; mi++)
#pragma unroll
        for (int ni = 0; ni < 4; ni++) {
            int r = wm0 + mi * 16 + (lane >> 2);
            int c = wn0 + ni * 8 + (lane & 3) * 2;
            *(float2*)(Cs + r * 132 + c)       = make_float2(acc[mi][ni][0], acc[mi][ni][1]);
            *(float2*)(Cs + (r + 8) * 132 + c) = make_float2(acc[mi][ni][2], acc[mi][ni][3]);
        }
    __syncthreads();

    for (int idx = tid; idx < 128 * 32; idx += 256) {
        int row = idx >> 5, c = (idx & 31) * 4;
        if (c >= ncols) continue;
        float4 v = *(float4*)(Cs + row * 132 + c);
        float b = bias_s[row];
        v.x += b; v.y += b; v.z += b; v.w += b;
        if (!isRes) {
            __half2 h0 = __floats2half2_rn(v.x, v.y);
            __half2 h1 = __floats2half2_rn(v.z, v.w);
            uint2 pk; pk.x = *(unsigned*)&h0; pk.y = *(unsigned*)&h1;
            *(uint2*)(g_feat + (size_t)((rg * Nn + n) * COUT + row) * VT + c0 + c) = pk;
        } else {
            *(float4*)(out + (size_t)(n * COUT + row) * VT + c0 + c) = v;
        }
    }
}

// ---------------------------------------------------------------------------
// kC_m: per (o, n): Out[25 x 300] = A[25 x 75] @ feat[75 x 300] (fp16 mma),
// then bn + residual(read from out) + relu. 256 threads (8 warps x 40 cols).
// (exact R7 version — measured 163.9us)
// ---------------------------------------------------------------------------
#define FS  312
#define CSd 308
#define KCM_A   (80 * FS * 2)          // 49920
#define KCM_SMEM (KCM_A + 32 * 80 * 2) // 55040
__global__ void __launch_bounds__(256)
kC_m(const float* __restrict__ bn_g, const float* __restrict__ bn_b,
     const float* __restrict__ bn_m, const float* __restrict__ bn_v,
     float* __restrict__ out) {
    extern __shared__ char sm[];
    __half* feat_s = (__half*)sm;           // [k=sw 80][t FS]
    __half* A_s    = (__half*)(sm + KCM_A); // [v 32][k 80]
    float*  Cs     = (float*)sm;            // reuse: [32][CSd]

    int tid = threadIdx.x;
    int wid = tid >> 5, lane = tid & 31;
    int o = blockIdx.x, n = blockIdx.y;

    // stage feat fp16 (zero-padded to 80 x 312) — scalar unsigned (R7)
    for (int idx = tid; idx < 80 * 156; idx += 256) {
        int row = idx / 156, c2 = (idx % 156) * 2;
        unsigned val = 0;
        if (row < 75 && c2 < 300) {
            int s = row / 25, w = row % 25;
            val = *(const unsigned*)(g_feat + (size_t)((s * Nn + n) * COUT + o) * VT + w * 300 + c2);
        }
        *(unsigned*)(feat_s + row * FS + c2) = val;
    }
    // stage A fp16 (zero-padded to 32 x 80)
    for (int idx = tid; idx < 32 * 80; idx += 256) {
        int v = idx / 80, k = idx % 80;
        float av = 0.f;
        if (v < 25 && k < 75) {
            int s = k / 25, w = k % 25;
            av = g_A[(size_t)((s * Nn + n) * COUT + o) * VV + v * 25 + w];
        }
        A_s[v * 80 + k] = __float2half_rn(av);
    }
    __syncthreads();

    uint32_t sb = smem_u32(sm);
    int wn0 = wid * 40;

    float acc[2][5][4];
#pragma unroll
    for (int mi = 0; mi < 2; mi++)
#pragma unroll
        for (int ni = 0; ni < 5; ni++)
#pragma unroll
            for (int q = 0; q < 4; q++) acc[mi][ni][q] = 0.f;

#pragma unroll
    for (int k0 = 0; k0 < 80; k0 += 16) {
        uint32_t a[2][4];
#pragma unroll
        for (int mi = 0; mi < 2; mi++) {
            int row = mi * 16 + (lane & 15);
            int col = k0 + (lane >> 4) * 8;
            LDSM_X4(a[mi], sb + KCM_A + (uint32_t)(row * 80 + col) * 2);
        }
        uint32_t b[5][2];
#pragma unroll
        for (int ni = 0; ni < 5; ni++) {
            int krow = k0 + (lane & 15);
            LDSM_X2T(b[ni], sb + (uint32_t)(krow * FS + wn0 + ni * 8) * 2);
        }
#pragma unroll
        for (int mi = 0; mi < 2; mi++)
#pragma unroll
            for (int ni = 0; ni < 5; ni++)
                MMA_F16(acc[mi][ni], a[mi], b[ni]);
    }

    __syncthreads();

#pragma unroll
    for (int mi = 0; mi < 2; mi++)
#pragma unroll
        for (int ni = 0; ni < 5; ni++) {
            int c = wn0 + ni * 8 + (lane & 3) * 2;
            if (c < 304) {
                int r = mi * 16 + (lane >> 2);
                *(float2*)(Cs + r * CSd + c)       = make_float2(acc[mi][ni][0], acc[mi][ni][1]);
                *(float2*)(Cs + (r + 8) * CSd + c) = make_float2(acc[mi][ni][2], acc[mi][ni][3]);
            }
        }
    __syncthreads();

    float scale = bn_g[o] * rsqrtf(bn_v[o] + EPSf);
    float shift = bn_b[o] - bn_m[o] * scale;
    for (int idx = tid; idx < 25 * 75; idx += 256) {
        int v = idx / 75, t4 = (idx % 75) * 4;
        float4 g = *(float4*)(Cs + v * CSd + t4);
        float* op = out + ((size_t)n * COUT + o) * VT + v * 300 + t4;
        float4 r = *(float4*)op;
        r.x = fmaxf(fmaf(g.x, scale, shift) + r.x, 0.f);
        r.y = fmaxf(fmaf(g.y, scale, shift) + r.y, 0.f);
        r.z = fmaxf(fmaf(g.z, scale, shift) + r.z, 0.f);
        r.w = fmaxf(fmaf(g.w, scale, shift) + r.w, 0.f);
        *(float4*)op = r;
    }
}

// ---------------------------------------------------------------------------
extern "C" void kernel_launch(void* const* d_in, const int* in_sizes, int n_in,
                              void* d_out, int out_size) {
    const float* x       = (const float*)d_in[0];
    const float* ada_A   = (const float*)d_in[1];
    const float* PA      = (const float*)d_in[2];
    const float* conv3_w = (const float*)d_in[3];
    const float* conv3_b = (const float*)d_in[4];
    const float* ada_w   = (const float*)d_in[5];
    const float* ada_b   = (const float*)d_in[6];
    const float* bn_g    = (const float*)d_in[7];
    const float* bn_b    = (const float*)d_in[8];
    const float* bn_m    = (const float*)d_in[9];
    const float* bn_v    = (const float*)d_in[10];
    const float* down_w  = (const float*)d_in[11];
    const float* down_b  = (const float*)d_in[12];
    const float* dbn_g   = (const float*)d_in[13];
    const float* dbn_b   = (const float*)d_in[14];
    const float* dbn_m   = (const float*)d_in[15];
    const float* dbn_v   = (const float*)d_in[16];
    float* out = (float*)d_out;

    cudaFuncSetAttribute(kA,   cudaFuncAttributeMaxDynamicSharedMemorySize, KA_SMEM);
    cudaFuncSetAttribute(kB_m, cudaFuncAttributeMaxDynamicSharedMemorySize, KBM_SMEM);
    cudaFuncSetAttribute(kC_m, cudaFuncAttributeMaxDynamicSharedMemorySize, KCM_SMEM);

    kX<<<(Nn * CIN * VT / 4 + 255) / 256, 256>>>(x);
    kW<<<64, 512>>>(conv3_w, conv3_b, down_w, down_b, dbn_g, dbn_b, dbn_m, dbn_v);
    kA<<<dim3(20, Nn, Ss), 128, KA_SMEM>>>(ada_A, PA, ada_w, ada_b);
    kB_m<<<dim3(59, 4, Nn), 256, KBM_SMEM>>>(out);
    kC_m<<<dim3(COUT, Nn), 256, KCM_SMEM>>>(bn_g, bn_b, bn_m, bn_v, out);
}

// round 10
// speedup vs baseline: 1.1584x; 1.1298x over previous
#include <cuda_runtime.h>
#include <cuda_fp16.h>
#include <cuda_bf16.h>
#include <cstdint>

#define Nn   32
#define CIN  64
#define COUT 128
#define Vv   25
#define Tlen 300
#define Ss   3
#define VT   7500
#define VV   625
#define EPSf 1e-5f

typedef unsigned long long u64;

// ---- device scratch (allocation-free) ----
__device__ __align__(16) __half g_feat[Ss * Nn * COUT * VT]; // [s][n][o][w*300+t] (184.3 MB)
__device__ __align__(16) float  g_A[Ss * Nn * COUT * VV];    // [s][n][o][v*25+w]  (30.7 MB)
__device__ __align__(16) __half g_Xhi[Nn * CIN * VT];        // fp16 hi of x (30.7 MB)
__device__ __align__(16) __half g_Xlo[Nn * CIN * VT];        // fp16 lo of x (30.7 MB)
__device__ __align__(16) __half g_Whi[512 * 64];
__device__ __align__(16) __half g_Wlo[512 * 64];
__device__ __align__(16) float g_bias[512];

// ---- scalar/FMA2 helpers ----
__device__ __forceinline__ void fma2(u64& d, u64 a, u64 b) {
    asm("fma.rn.f32x2 %0, %1, %2, %0;" : "+l"(d) : "l"(a), "l"(b));
}
__device__ __forceinline__ u64 dup2(float v) {
    u64 r; asm("mov.b64 %0, {%1, %1};" : "=l"(r) : "f"(v)); return r;
}
__device__ __forceinline__ u64 pack2(float lo, float hi) {
    u64 r; asm("mov.b64 %0, {%1, %2};" : "=l"(r) : "f"(lo), "f"(hi)); return r;
}
__device__ __forceinline__ float lo32(u64 v) { return __uint_as_float((unsigned)v); }
__device__ __forceinline__ float hi32(u64 v) { return __uint_as_float((unsigned)(v >> 32)); }

__device__ __forceinline__ uint32_t smem_u32(const void* p) {
    uint32_t a;
    asm("{ .reg .u64 t; cvta.to.shared.u64 t, %1; cvt.u32.u64 %0, t; }" : "=r"(a) : "l"(p));
    return a;
}

// ---- mma.sync / ldmatrix (sm_80+, no arch-'a' gating) ----
#define LDSM_X4(r, addr) \
    asm volatile("ldmatrix.sync.aligned.m8n8.x4.shared.b16 {%0,%1,%2,%3}, [%4];" \
        : "=r"((r)[0]), "=r"((r)[1]), "=r"((r)[2]), "=r"((r)[3]) : "r"(addr))
#define LDSM_X2T(r, addr) \
    asm volatile("ldmatrix.sync.aligned.m8n8.x2.trans.shared.b16 {%0,%1}, [%2];" \
        : "=r"((r)[0]), "=r"((r)[1]) : "r"(addr))
#define MMA_F16(d, a, b) \
    asm volatile("mma.sync.aligned.m16n8k16.row.col.f32.f16.f16.f32 " \
        "{%0,%1,%2,%3}, {%4,%5,%6,%7}, {%8,%9}, {%0,%1,%2,%3};" \
        : "+f"((d)[0]), "+f"((d)[1]), "+f"((d)[2]), "+f"((d)[3]) \
        : "r"((a)[0]), "r"((a)[1]), "r"((a)[2]), "r"((a)[3]), "r"((b)[0]), "r"((b)[1]))

// ---------------------------------------------------------------------------
// kX: pre-split x (fp32) into fp16 hi/lo, linear layout identical to x.
// ---------------------------------------------------------------------------
__global__ void kX(const float* __restrict__ x) {
    size_t i4 = ((size_t)blockIdx.x * blockDim.x + threadIdx.x) * 4;
    if (i4 >= (size_t)Nn * CIN * VT) return;
    float4 v = *(const float4*)(x + i4);
    __half h0 = __float2half_rn(v.x), h1 = __float2half_rn(v.y);
    __half h2 = __float2half_rn(v.z), h3 = __float2half_rn(v.w);
    __half2 p0(h0, h1), p1(h2, h3);
    uint2 ph; ph.x = *(unsigned*)&p0; ph.y = *(unsigned*)&p1;
    *(uint2*)(g_Xhi + i4) = ph;
    __half2 q0(__float2half_rn(v.x - __half2float(h0)), __float2half_rn(v.y - __half2float(h1)));
    __half2 q1(__float2half_rn(v.z - __half2float(h2)), __float2half_rn(v.w - __half2float(h3)));
    uint2 pl; pl.x = *(unsigned*)&q0; pl.y = *(unsigned*)&q1;
    *(uint2*)(g_Xlo + i4) = pl;
}

// ---------------------------------------------------------------------------
// kW: split folded W into fp16 hi/lo + bias
// ---------------------------------------------------------------------------
__global__ void kW(const float* __restrict__ conv3_w, const float* __restrict__ conv3_b,
                   const float* __restrict__ down_w,  const float* __restrict__ down_b,
                   const float* __restrict__ dg, const float* __restrict__ dbeta,
                   const float* __restrict__ dm, const float* __restrict__ dvar) {
    int idx = blockIdx.x * blockDim.x + threadIdx.x;
    if (idx >= 512 * 64) return;
    int r = idx >> 6, k = idx & 63;
    float w;
    if (r < Ss * COUT) {
        w = conv3_w[r * CIN + k];
    } else {
        int o = r - Ss * COUT;
        w = dg[o] * rsqrtf(dvar[o] + EPSf) * down_w[o * CIN + k];
    }
    __half hi = __float2half_rn(w);
    g_Whi[idx] = hi;
    g_Wlo[idx] = __float2half_rn(w - __half2float(hi));
    if (k == 0) {
        float b;
        if (r < Ss * COUT) b = conv3_b[r];
        else {
            int o = r - Ss * COUT;
            float sc = dg[o] * rsqrtf(dvar[o] + EPSf);
            b = sc * (down_b[o] - dm[o]) + dbeta[o];
        }
        g_bias[r] = b;
    }
}

// ---------------------------------------------------------------------------
// kA: g_A = (ada_w . ada_A + ada_b) * PA. grid (20, n, s), 128 threads, FMA2.
// ---------------------------------------------------------------------------
#define KA_SMEM (64 * 16 * 8 + 64 * 125 * 4 + 32 * 4)
__global__ void __launch_bounds__(128)
kA(const float* __restrict__ adaA, const float* __restrict__ PA,
   const float* __restrict__ ada_w, const float* __restrict__ ada_b) {
    extern __shared__ char smA[];
    u64*   Wp  = (u64*)smA;
    float* Xa  = (float*)(smA + 64 * 16 * 8);
    float* bsm = (float*)(smA + 64 * 16 * 8 + 64 * 125 * 4);

    int tid = threadIdx.x;
    int s = blockIdx.z, n = blockIdx.y;
    int g = blockIdx.x & 3;
    int vw0 = (blockIdx.x >> 2) * 125;

    const float* wsrc = ada_w + s * COUT * CIN + g * 32 * CIN;
    for (int idx = tid; idx < 64 * 16; idx += 128) {
        int i = idx >> 4, op = idx & 15;
        Wp[i * 16 + op] = pack2(wsrc[(2 * op) * CIN + i], wsrc[(2 * op + 1) * CIN + i]);
    }
    for (int idx = tid; idx < 64 * 125; idx += 128) {
        int i = idx / 125, j = idx % 125;
        Xa[i * 125 + j] = adaA[(size_t)(n * CIN + i) * VV + vw0 + j];
    }
    if (tid < 32) bsm[tid] = ada_b[s * COUT + g * 32 + tid];
    __syncthreads();
    if (tid >= 125) return;

    int vw = vw0 + tid;
    float pa = PA[s * VV + vw];

    u64 acc[16];
#pragma unroll
    for (int p = 0; p < 16; p++) acc[p] = 0ull;

#pragma unroll 8
    for (int i = 0; i < CIN; i++) {
        u64 f2 = dup2(Xa[i * 125 + tid]);
        const ulonglong2* wr = (const ulonglong2*)(Wp + i * 16);
#pragma unroll
        for (int p = 0; p < 8; p++) {
            ulonglong2 wv = wr[p];
            fma2(acc[2 * p],     wv.x, f2);
            fma2(acc[2 * p + 1], wv.y, f2);
        }
    }
    float* outp = g_A + ((size_t)((s * Nn + n) * COUT) + g * 32) * VV + vw;
#pragma unroll
    for (int p = 0; p < 16; p++) {
        outp[(size_t)(2 * p) * VV]     = (lo32(acc[p]) + bsm[2 * p])     * pa;
        outp[(size_t)(2 * p + 1) * VV] = (hi32(acc[p]) + bsm[2 * p + 1]) * pa;
    }
}

// ---------------------------------------------------------------------------
// kB_m: tensor GEMM C[128r x 128c] = W[128x64] @ X[64 x 128c].
// 512 threads, 16 warps in 4M x 4N layout, warp tile 32x32 (acc=32 regs).
// __launch_bounds__(512,2) caps regs -> 2 CTAs/SM = 32 warps (50% occ).
// rg<3: 1 MMA term -> g_feat fp16; rg==3: 3 terms (split fp16) -> d_out fp32.
// grid (59, 4, 32).
// ---------------------------------------------------------------------------
#define PADK 72
#define PADC 136
#define WHI_OFF 0
#define WLO_OFF (128 * PADK * 2)                // 18432
#define XHI_OFF (WLO_OFF + 128 * PADK * 2)      // 36864
#define XLO_OFF (XHI_OFF + 64 * PADC * 2)       // 54272
#define BIAS_OFF (XLO_OFF + 64 * PADC * 2)      // 71680
#define KBM_SMEM (BIAS_OFF + 128 * 4)           // 72192
__global__ void __launch_bounds__(512, 2)
kB_m(float* __restrict__ out) {
    extern __shared__ char sm[];
    __half* Whi_s = (__half*)(sm + WHI_OFF);
    __half* Wlo_s = (__half*)(sm + WLO_OFF);
    __half* Xhi_s = (__half*)(sm + XHI_OFF);
    __half* Xlo_s = (__half*)(sm + XLO_OFF);
    float* bias_s = (float*)(sm + BIAS_OFF);
    float* Cs = (float*)sm;   // reuse after mainloop: [128][132] = 67584 B

    int tid = threadIdx.x;
    int wid = tid >> 5, lane = tid & 31;
    int n = blockIdx.z, rg = blockIdx.y;
    int c0 = blockIdx.x * 128;
    int r0 = rg * 128;
    int ncols = VT - c0; if (ncols > 128) ncols = 128;   // 128 or 76 (mult of 4)
    bool isRes = (rg == 3);

    // ---- stage W hi (and lo only for residual rg) ----
    for (int idx = tid; idx < 1024; idx += 512) {
        int row = idx >> 3, kc = (idx & 7) * 8;
        uint4 v = *(const uint4*)(g_Whi + (size_t)(r0 + row) * 64 + kc);
        *(uint4*)(Whi_s + row * PADK + kc) = v;
    }
    if (isRes) {
        for (int idx = tid; idx < 1024; idx += 512) {
            int row = idx >> 3, kc = (idx & 7) * 8;
            uint4 v = *(const uint4*)(g_Wlo + (size_t)(r0 + row) * 64 + kc);
            *(uint4*)(Wlo_s + row * PADK + kc) = v;
        }
    }
    if (tid < 128) bias_s[tid] = g_bias[r0 + tid];

    // ---- stage X [k][c] fp16 straight copy (uint2; row base 8B-aligned) ----
    for (int idx = tid; idx < 64 * 32; idx += 512) {
        int k = idx >> 5, c4 = (idx & 31) << 2;
        uint2 v = make_uint2(0u, 0u);
        if (c4 < ncols) v = *(const uint2*)(g_Xhi + (size_t)(n * CIN + k) * VT + c0 + c4);
        *(uint2*)(Xhi_s + k * PADC + c4) = v;
        if (isRes) {
            uint2 vl = make_uint2(0u, 0u);
            if (c4 < ncols) vl = *(const uint2*)(g_Xlo + (size_t)(n * CIN + k) * VT + c0 + c4);
            *(uint2*)(Xlo_s + k * PADC + c4) = vl;
        }
    }
    __syncthreads();

    int wm0 = (wid & 3) * 32;          // 4 M groups of 32
    int wn0 = (wid >> 2) * 32;         // 4 N groups of 32
    uint32_t sbase = smem_u32(sm);

    float acc[2][4][4];
#pragma unroll
    for (int mi = 0; mi < 2; mi++)
#pragma unroll
        for (int ni = 0; ni < 4; ni++)
#pragma unroll
            for (int q = 0; q < 4; q++) acc[mi][ni][q] = 0.f;

#pragma unroll
    for (int k0 = 0; k0 < 64; k0 += 16) {
        uint32_t a_hi[2][4], b_hi[4][2];
#pragma unroll
        for (int mi = 0; mi < 2; mi++) {
            int row = wm0 + mi * 16 + (lane & 15);
            int col = k0 + (lane >> 4) * 8;
            LDSM_X4(a_hi[mi], sbase + WHI_OFF + (uint32_t)(row * PADK + col) * 2);
        }
#pragma unroll
        for (int ni = 0; ni < 4; ni++) {
            int krow = k0 + (lane & 15);
            LDSM_X2T(b_hi[ni], sbase + XHI_OFF + (uint32_t)(krow * PADC + wn0 + ni * 8) * 2);
        }
#pragma unroll
        for (int mi = 0; mi < 2; mi++)
#pragma unroll
            for (int ni = 0; ni < 4; ni++)
                MMA_F16(acc[mi][ni], a_hi[mi], b_hi[ni]);

        if (isRes) {
            uint32_t a_lo[2][4], b_lo[4][2];
#pragma unroll
            for (int mi = 0; mi < 2; mi++) {
                int row = wm0 + mi * 16 + (lane & 15);
                int col = k0 + (lane >> 4) * 8;
                LDSM_X4(a_lo[mi], sbase + WLO_OFF + (uint32_t)(row * PADK + col) * 2);
            }
#pragma unroll
            for (int ni = 0; ni < 4; ni++) {
                int krow = k0 + (lane & 15);
                LDSM_X2T(b_lo[ni], sbase + XLO_OFF + (uint32_t)(krow * PADC + wn0 + ni * 8) * 2);
            }
#pragma unroll
            for (int mi = 0; mi < 2; mi++)
#pragma unroll
                for (int ni = 0; ni < 4; ni++) {
                    MMA_F16(acc[mi][ni], a_hi[mi], b_lo[ni]);
                    MMA_F16(acc[mi][ni], a_lo[mi], b_hi[ni]);
                }
        }
    }

    __syncthreads();

#pragma unroll
    for (int mi = 0; mi < 2; mi++)
#pragma unroll
        for (int ni = 0; ni < 4; ni++) {
            int r = wm0 + mi * 16 + (lane >> 2);
            int c = wn0 + ni * 8 + (lane & 3) * 2;
            *(float2*)(Cs + r * 132 + c)       = make_float2(acc[mi][ni][0], acc[mi][ni][1]);
            *(float2*)(Cs + (r + 8) * 132 + c) = make_float2(acc[mi][ni][2], acc[mi][ni][3]);
        }
    __syncthreads();

    for (int idx = tid; idx < 128 * 32; idx += 512) {
        int row = idx >> 5, c = (idx & 31) * 4;
        if (c >= ncols) continue;
        float4 v = *(float4*)(Cs + row * 132 + c);
        float b = bias_s[row];
        v.x += b; v.y += b; v.z += b; v.w += b;
        if (!isRes) {
            __half2 h0 = __floats2half2_rn(v.x, v.y);
            __half2 h1 = __floats2half2_rn(v.z, v.w);
            uint2 pk; pk.x = *(unsigned*)&h0; pk.y = *(unsigned*)&h1;
            *(uint2*)(g_feat + (size_t)((rg * Nn + n) * COUT + row) * VT + c0 + c) = pk;
        } else {
            *(float4*)(out + (size_t)(n * COUT + row) * VT + c0 + c) = v;
        }
    }
}

// ---------------------------------------------------------------------------
// kC_m: per (o, n): Out[25 x 300] = A[25 x 75] @ feat[75 x 300] (fp16 mma),
// then bn + residual(read from out) + relu. 256 threads (8 warps x 40 cols).
// (exact R7 version — measured 163.9us)
// ---------------------------------------------------------------------------
#define FS  312
#define CSd 308
#define KCM_A   (80 * FS * 2)          // 49920
#define KCM_SMEM (KCM_A + 32 * 80 * 2) // 55040
__global__ void __launch_bounds__(256)
kC_m(const float* __restrict__ bn_g, const float* __restrict__ bn_b,
     const float* __restrict__ bn_m, const float* __restrict__ bn_v,
     float* __restrict__ out) {
    extern __shared__ char sm[];
    __half* feat_s = (__half*)sm;           // [k=sw 80][t FS]
    __half* A_s    = (__half*)(sm + KCM_A); // [v 32][k 80]
    float*  Cs     = (float*)sm;            // reuse: [32][CSd]

    int tid = threadIdx.x;
    int wid = tid >> 5, lane = tid & 31;
    int o = blockIdx.x, n = blockIdx.y;

    // stage feat fp16 (zero-padded to 80 x 312) — scalar unsigned (R7)
    for (int idx = tid; idx < 80 * 156; idx += 256) {
        int row = idx / 156, c2 = (idx % 156) * 2;
        unsigned val = 0;
        if (row < 75 && c2 < 300) {
            int s = row / 25, w = row % 25;
            val = *(const unsigned*)(g_feat + (size_t)((s * Nn + n) * COUT + o) * VT + w * 300 + c2);
        }
        *(unsigned*)(feat_s + row * FS + c2) = val;
    }
    // stage A fp16 (zero-padded to 32 x 80)
    for (int idx = tid; idx < 32 * 80; idx += 256) {
        int v = idx / 80, k = idx % 80;
        float av = 0.f;
        if (v < 25 && k < 75) {
            int s = k / 25, w = k % 25;
            av = g_A[(size_t)((s * Nn + n) * COUT + o) * VV + v * 25 + w];
        }
        A_s[v * 80 + k] = __float2half_rn(av);
    }
    __syncthreads();

    uint32_t sb = smem_u32(sm);
    int wn0 = wid * 40;

    float acc[2][5][4];
#pragma unroll
    for (int mi = 0; mi < 2; mi++)
#pragma unroll
        for (int ni = 0; ni < 5; ni++)
#pragma unroll
            for (int q = 0; q < 4; q++) acc[mi][ni][q] = 0.f;

#pragma unroll
    for (int k0 = 0; k0 < 80; k0 += 16) {
        uint32_t a[2][4];
#pragma unroll
        for (int mi = 0; mi < 2; mi++) {
            int row = mi * 16 + (lane & 15);
            int col = k0 + (lane >> 4) * 8;
            LDSM_X4(a[mi], sb + KCM_A + (uint32_t)(row * 80 + col) * 2);
        }
        uint32_t b[5][2];
#pragma unroll
        for (int ni = 0; ni < 5; ni++) {
            int krow = k0 + (lane & 15);
            LDSM_X2T(b[ni], sb + (uint32_t)(krow * FS + wn0 + ni * 8) * 2);
        }
#pragma unroll
        for (int mi = 0; mi < 2; mi++)
#pragma unroll
            for (int ni = 0; ni < 5; ni++)
                MMA_F16(acc[mi][ni], a[mi], b[ni]);
    }

    __syncthreads();

#pragma unroll
    for (int mi = 0; mi < 2; mi++)
#pragma unroll
        for (int ni = 0; ni < 5; ni++) {
            int c = wn0 + ni * 8 + (lane & 3) * 2;
            if (c < 304) {
                int r = mi * 16 + (lane >> 2);
                *(float2*)(Cs + r * CSd + c)       = make_float2(acc[mi][ni][0], acc[mi][ni][1]);
                *(float2*)(Cs + (r + 8) * CSd + c) = make_float2(acc[mi][ni][2], acc[mi][ni][3]);
            }
        }
    __syncthreads();

    float scale = bn_g[o] * rsqrtf(bn_v[o] + EPSf);
    float shift = bn_b[o] - bn_m[o] * scale;
    for (int idx = tid; idx < 25 * 75; idx += 256) {
        int v = idx / 75, t4 = (idx % 75) * 4;
        float4 g = *(float4*)(Cs + v * CSd + t4);
        float* op = out + ((size_t)n * COUT + o) * VT + v * 300 + t4;
        float4 r = *(float4*)op;
        r.x = fmaxf(fmaf(g.x, scale, shift) + r.x, 0.f);
        r.y = fmaxf(fmaf(g.y, scale, shift) + r.y, 0.f);
        r.z = fmaxf(fmaf(g.z, scale, shift) + r.z, 0.f);
        r.w = fmaxf(fmaf(g.w, scale, shift) + r.w, 0.f);
        *(float4*)op = r;
    }
}

// ---------------------------------------------------------------------------
extern "C" void kernel_launch(void* const* d_in, const int* in_sizes, int n_in,
                              void* d_out, int out_size) {
    const float* x       = (const float*)d_in[0];
    const float* ada_A   = (const float*)d_in[1];
    const float* PA      = (const float*)d_in[2];
    const float* conv3_w = (const float*)d_in[3];
    const float* conv3_b = (const float*)d_in[4];
    const float* ada_w   = (const float*)d_in[5];
    const float* ada_b   = (const float*)d_in[6];
    const float* bn_g    = (const float*)d_in[7];
    const float* bn_b    = (const float*)d_in[8];
    const float* bn_m    = (const float*)d_in[9];
    const float* bn_v    = (const float*)d_in[10];
    const float* down_w  = (const float*)d_in[11];
    const float* down_b  = (const float*)d_in[12];
    const float* dbn_g   = (const float*)d_in[13];
    const float* dbn_b   = (const float*)d_in[14];
    const float* dbn_m   = (const float*)d_in[15];
    const float* dbn_v   = (const float*)d_in[16];
    float* out = (float*)d_out;

    cudaFuncSetAttribute(kA,   cudaFuncAttributeMaxDynamicSharedMemorySize, KA_SMEM);
    cudaFuncSetAttribute(kB_m, cudaFuncAttributeMaxDynamicSharedMemorySize, KBM_SMEM);
    cudaFuncSetAttribute(kC_m, cudaFuncAttributeMaxDynamicSharedMemorySize, KCM_SMEM);

    kX<<<(Nn * CIN * VT / 4 + 255) / 256, 256>>>(x);
    kW<<<64, 512>>>(conv3_w, conv3_b, down_w, down_b, dbn_g, dbn_b, dbn_m, dbn_v);
    kA<<<dim3(20, Nn, Ss), 128, KA_SMEM>>>(ada_A, PA, ada_w, ada_b);
    kB_m<<<dim3(59, 4, Nn), 512, KBM_SMEM>>>(out);
    kC_m<<<dim3(COUT, Nn), 256, KCM_SMEM>>>(bn_g, bn_b, bn_m, bn_v, out);
}